// round 7
// baseline (speedup 1.0000x reference)
#include <cuda_runtime.h>
#include <cuda_bf16.h>
#include <cstdint>

#define N_NODES 50000
#define E_EDGES 800000
#define NB_SCAN 196   // ceil(50000/256)
#define NB_CSR  444   // csr grid: 3 blocks/SM * 148 SMs

// ---------------- device scratch (static, no allocs) ----------------
__device__ __align__(16) float  d_P[(size_t)N_NODES * 256];   // packed, see layout
__device__ __align__(16) float  d_y0[(size_t)N_NODES * 64];
__device__ __align__(16) float  d_y1[(size_t)N_NODES * 64];
__device__ int    d_src[E_EDGES];
__device__ int    d_dst[E_EDGES];
__device__ int    d_deg[N_NODES];
__device__ int    d_fill[N_NODES];
__device__ int    d_rowptr[N_NODES + 1];
__device__ int    d_bsum[NB_SCAN];
__device__ int    d_boff[NB_SCAN];
__device__ int    d_esrc[E_EDGES];
__device__ __align__(16) float  d_ea_s[(size_t)E_EDGES * 16]; // edge_attr permuted to CSR order
__device__ __align__(16) float  d_Wnode[2][64 * 256];         // packed-column node weights
__device__ __align__(16) float  d_WqT[2][128 * 16];           // edge-attr weights, [chan][k]
__device__ float  d_bias2[2][256];
__device__ float  d_psum[NB_CSR * 64];                        // per-csr-block BN partials
__device__ float  d_psq[NB_CSR * 64];
__device__ __align__(16) float  d_scale[2][64];
__device__ __align__(16) float  d_shift[2][64];
__device__ int    d_bound[65];
__device__ int    d_ei64;
__device__ int    d_b64;

// Packed P layout per node (256 floats):
//   dst region [0,128):   for channel c: fd at (c>>1)*4+(c&1), sd at +2
//   src region [128,256): same mapping + 128  (fs / ss)
__device__ __forceinline__ int idx_fd(int c) { return ((c >> 1) << 2) + (c & 1); }

__device__ __forceinline__ float sigmoid_f(float x) {
    float t;
    asm("tanh.approx.f32 %0, %1;" : "=f"(t) : "f"(x * 0.5f));
    return fmaf(0.5f, t, 0.5f);
}
__device__ __forceinline__ float softplus_f(float x) {
    return (x > 20.f) ? x : __logf(1.f + __expf(x));
}
__device__ __forceinline__ uint64_t fma2(uint64_t a, uint64_t b, uint64_t c) {
    uint64_t d;
    asm("fma.rn.f32x2 %0, %1, %2, %3;" : "=l"(d) : "l"(a), "l"(b), "l"(c));
    return d;
}
__device__ __forceinline__ float2 unpack2(uint64_t v) {
    float2 r;
    asm("mov.b64 {%0, %1}, %2;" : "=f"(r.x), "=f"(r.y) : "l"(v));
    return r;
}

// one edge's message, accumulated into acc0/acc1 (2 channels per lane)
__device__ __forceinline__ void edge_accum(
    const uint64_t* wq0, const uint64_t* wq1, const uint64_t* wq2, const uint64_t* wq3,
    ulonglong2 a0, ulonglong2 a1, ulonglong2 a2, ulonglong2 a3,
    float4 dp, float4 sp, float& acc0, float& acc1)
{
    uint64_t ep[8] = {a0.x, a0.y, a1.x, a1.y, a2.x, a2.y, a3.x, a3.y};
    uint64_t qf0 = 0, qf1 = 0, qs0 = 0, qs1 = 0;
    #pragma unroll
    for (int k = 0; k < 8; k++) {
        qf0 = fma2(wq0[k], ep[k], qf0);
        qf1 = fma2(wq1[k], ep[k], qf1);
        qs0 = fma2(wq2[k], ep[k], qs0);
        qs1 = fma2(wq3[k], ep[k], qs1);
    }
    float2 h0 = unpack2(qf0), h1 = unpack2(qf1), h2 = unpack2(qs0), h3 = unpack2(qs1);
    float f0 = dp.x + sp.x + (h0.x + h0.y);
    float f1 = dp.y + sp.y + (h1.x + h1.y);
    float s0 = dp.z + sp.z + (h2.x + h2.y);
    float s1 = dp.w + sp.w + (h3.x + h3.y);
    acc0 += sigmoid_f(f0) * softplus_f(s0);
    acc1 += sigmoid_f(f1) * softplus_f(s1);
}

// ---------------- zero counters + dtype detection ----------------
__global__ void zero_detect_kernel(const int* __restrict__ ei32, const int* __restrict__ b32) {
    int stride = gridDim.x * blockDim.x;
    for (int i = blockIdx.x * blockDim.x + threadIdx.x; i < N_NODES; i += stride) {
        d_deg[i] = 0; d_fill[i] = 0;
    }
    if (blockIdx.x == 0 && threadIdx.x == 0) {
        int o = 0;
        #pragma unroll
        for (int i = 1; i < 64; i += 2) o |= ei32[i];
        d_ei64 = (o == 0) ? 1 : 0;
        d_b64 = (b32[N_NODES - 1] == 0) ? 1 : 0;
    }
}

// ---------------- prep: decode+clamp indices (+hist), pack weights ----------------
__global__ void prep_kernel(const void* __restrict__ ei_raw,
                            const float* __restrict__ Wf0, const float* __restrict__ Ws0,
                            const float* __restrict__ bf0, const float* __restrict__ bs0,
                            const float* __restrict__ Wf1, const float* __restrict__ Ws1,
                            const float* __restrict__ bf1, const float* __restrict__ bs1) {
    int stride = gridDim.x * blockDim.x;
    int gid = blockIdx.x * blockDim.x + threadIdx.x;
    const int ei64 = d_ei64;
    const long long* eL = (const long long*)ei_raw;
    const int*       eI = (const int*)ei_raw;
    for (int i = gid; i < E_EDGES; i += stride) {
        int s, d;
        if (ei64) { s = (int)eL[i]; d = (int)eL[E_EDGES + i]; }
        else      { s = eI[i];      d = eI[E_EDGES + i]; }
        s = min(max(s, 0), N_NODES - 1);
        d = min(max(d, 0), N_NODES - 1);
        d_src[i] = s;
        d_dst[i] = d;
        atomicAdd(&d_deg[d], 1);
    }
    for (int i = gid; i < 2 * 64 * 144; i += stride) {
        int l = i / 9216; int r = i % 9216; int j = r / 144; int k = r % 144;
        const float* Wf = l ? Wf1 : Wf0;
        const float* Ws = l ? Ws1 : Ws0;
        float wf = Wf[j * 144 + k], ws = Ws[j * 144 + k];
        int pf = idx_fd(j);
        if (k < 64) {
            d_Wnode[l][k * 256 + pf]     = wf;
            d_Wnode[l][k * 256 + pf + 2] = ws;
        } else if (k < 128) {
            int kk = k - 64;
            d_Wnode[l][kk * 256 + 128 + pf]     = wf;
            d_Wnode[l][kk * 256 + 128 + pf + 2] = ws;
        } else {
            int kk = k - 128;
            d_WqT[l][j * 16 + kk]        = wf;
            d_WqT[l][(64 + j) * 16 + kk] = ws;
        }
    }
    for (int i = gid; i < 2 * 64; i += stride) {
        int l = i >> 6; int j = i & 63;
        const float* bf = l ? bf1 : bf0;
        const float* bs = l ? bs1 : bs0;
        int pf = idx_fd(j);
        d_bias2[l][pf]           = bf[j];
        d_bias2[l][pf + 2]       = bs[j];
        d_bias2[l][128 + pf]     = 0.f;
        d_bias2[l][128 + pf + 2] = 0.f;
    }
}

// ---------------- CSR scan: 3 small kernels ----------------
__global__ void scan1_kernel() {
    __shared__ int sh[256];
    int t = threadIdx.x;
    int i = blockIdx.x * 256 + t;
    sh[t] = (i < N_NODES) ? d_deg[i] : 0;
    __syncthreads();
    for (int off = 128; off > 0; off >>= 1) {
        if (t < off) sh[t] += sh[t + off];
        __syncthreads();
    }
    if (t == 0) d_bsum[blockIdx.x] = sh[0];
}

__global__ void scan2_kernel() {
    __shared__ int sh[256];
    int t = threadIdx.x;
    int v = (t < NB_SCAN) ? d_bsum[t] : 0;
    sh[t] = v;
    __syncthreads();
    for (int off = 1; off < 256; off <<= 1) {
        int u = (t >= off) ? sh[t - off] : 0;
        __syncthreads();
        sh[t] += u;
        __syncthreads();
    }
    if (t < NB_SCAN) d_boff[t] = sh[t] - v;
    if (t == 255) d_rowptr[N_NODES] = sh[255];
}

__global__ void scan3_kernel() {
    __shared__ int sh[256];
    int t = threadIdx.x;
    int i = blockIdx.x * 256 + t;
    int v = (i < N_NODES) ? d_deg[i] : 0;
    sh[t] = v;
    __syncthreads();
    for (int off = 1; off < 256; off <<= 1) {
        int u = (t >= off) ? sh[t - off] : 0;
        __syncthreads();
        sh[t] += u;
        __syncthreads();
    }
    if (i < N_NODES) d_rowptr[i] = sh[t] - v + d_boff[blockIdx.x];
}

__global__ void scatter_kernel(const float* __restrict__ ea) {
    int e = blockIdx.x * blockDim.x + threadIdx.x;
    if (e >= E_EDGES) return;
    int dn = d_dst[e];
    int pos = d_rowptr[dn] + atomicAdd(&d_fill[dn], 1);
    pos = min(max(pos, 0), E_EDGES - 1);
    d_esrc[pos] = d_src[e];
    const float4* A = (const float4*)&ea[(size_t)e * 16];
    float4* B = (float4*)&d_ea_s[(size_t)pos * 16];
    B[0] = A[0]; B[1] = A[1]; B[2] = A[2]; B[3] = A[3];
}

// ---------------- node GEMM: P[n][256] = in[n][64] @ Wnode + bias ----------------
__global__ __launch_bounds__(256) void node_gemm_kernel(const float* __restrict__ x_in, int layer) {
    __shared__ __align__(16) float sX[64 * 68];
    __shared__ float sB[256];
    __shared__ float sSc[64], sSh[64];
    int t = threadIdx.x;
    int n0 = blockIdx.x * 64;
    const float* __restrict__ src = layer ? d_y0 : x_in;
    const float* __restrict__ Wn = d_Wnode[layer];

    sB[t] = d_bias2[layer][t];
    if (t < 64) {
        sSc[t] = layer ? d_scale[0][t] : 1.f;
        sSh[t] = layer ? d_shift[0][t] : 0.f;
    }
    __syncthreads();
    {
        int n = t >> 2, q = t & 3;
        int node = n0 + n;
        #pragma unroll
        for (int i = 0; i < 4; i++) {
            int k = q * 16 + i * 4;
            float4 v = make_float4(0.f, 0.f, 0.f, 0.f);
            if (node < N_NODES) v = *(const float4*)&src[(size_t)node * 64 + k];
            sX[(k + 0) * 68 + n] = v.x * sSc[k + 0] + sSh[k + 0];
            sX[(k + 1) * 68 + n] = v.y * sSc[k + 1] + sSh[k + 1];
            sX[(k + 2) * 68 + n] = v.z * sSc[k + 2] + sSh[k + 2];
            sX[(k + 3) * 68 + n] = v.w * sSc[k + 3] + sSh[k + 3];
        }
    }
    __syncthreads();

    int tx = t & 31, ty = t >> 5;
    float acc[8][8];
    #pragma unroll
    for (int e = 0; e < 8; e++)
        #pragma unroll
        for (int j = 0; j < 8; j++) acc[e][j] = 0.f;

    #pragma unroll 8
    for (int k = 0; k < 64; k++) {
        float4 w0 = *(const float4*)&Wn[k * 256 + tx * 8];
        float4 w1 = *(const float4*)&Wn[k * 256 + tx * 8 + 4];
        float4 z0 = *(const float4*)&sX[k * 68 + ty * 8];
        float4 z1 = *(const float4*)&sX[k * 68 + ty * 8 + 4];
        float ww[8] = {w0.x, w0.y, w0.z, w0.w, w1.x, w1.y, w1.z, w1.w};
        float zz[8] = {z0.x, z0.y, z0.z, z0.w, z1.x, z1.y, z1.z, z1.w};
        #pragma unroll
        for (int e = 0; e < 8; e++)
            #pragma unroll
            for (int j = 0; j < 8; j++) acc[e][j] += zz[e] * ww[j];
    }

    float b[8];
    #pragma unroll
    for (int j = 0; j < 8; j++) b[j] = sB[tx * 8 + j];
    #pragma unroll
    for (int e = 0; e < 8; e++) {
        int node = n0 + ty * 8 + e;
        if (node < N_NODES) {
            float4 o0 = make_float4(acc[e][0] + b[0], acc[e][1] + b[1], acc[e][2] + b[2], acc[e][3] + b[3]);
            float4 o1 = make_float4(acc[e][4] + b[4], acc[e][5] + b[5], acc[e][6] + b[6], acc[e][7] + b[7]);
            *(float4*)&d_P[(size_t)node * 256 + tx * 8]     = o0;
            *(float4*)&d_P[(size_t)node * 256 + tx * 8 + 4] = o1;
        }
    }
}

// ---------------- CSR consumer: warp/row, lane = 2 channels, pair-pipelined ----------------
// Also accumulates per-block BN stats (sum, sumsq) -> d_psum/d_psq. No atomics.
__global__ __launch_bounds__(128, 3) void csr_kernel(const float* __restrict__ x_in, int layer) {
    __shared__ float sS[4][64], sQ[4][64];
    const float* __restrict__ WqT = d_WqT[layer];
    float* __restrict__ y = layer ? d_y1 : d_y0;
    int warp = threadIdx.x >> 5, lane = threadIdx.x & 31;
    int gwarp = blockIdx.x * 4 + warp;
    const int nwarps = NB_CSR * 4;
    int c0 = lane * 2;

    uint64_t wq0[8], wq1[8], wq2[8], wq3[8];
    {
        const uint64_t* W0 = (const uint64_t*)&WqT[c0 * 16];
        const uint64_t* W1 = (const uint64_t*)&WqT[(c0 + 1) * 16];
        const uint64_t* W2 = (const uint64_t*)&WqT[(64 + c0) * 16];
        const uint64_t* W3 = (const uint64_t*)&WqT[(65 + c0) * 16];
        #pragma unroll
        for (int k = 0; k < 8; k++) { wq0[k] = W0[k]; wq1[k] = W1[k]; wq2[k] = W2[k]; wq3[k] = W3[k]; }
    }
    float2 rs = make_float2(1.f, 1.f), rh = make_float2(0.f, 0.f);
    if (layer) {
        rs = *(const float2*)&d_scale[0][c0];
        rh = *(const float2*)&d_shift[0][c0];
    }

    float st_s0 = 0.f, st_s1 = 0.f, st_q0 = 0.f, st_q1 = 0.f;

    for (int row = gwarp; row < N_NODES; row += nwarps) {
        int e0 = d_rowptr[row], e1 = d_rowptr[row + 1];
        float4 dp = *(const float4*)&d_P[(size_t)row * 256 + lane * 4];
        float acc0 = 0.f, acc1 = 0.f;

        int e = e0;
        for (; e + 1 < e1; e += 2) {
            int sA = d_esrc[e], sB = d_esrc[e + 1];
            float4 spA = *(const float4*)&d_P[(size_t)sA * 256 + 128 + lane * 4];
            float4 spB = *(const float4*)&d_P[(size_t)sB * 256 + 128 + lane * 4];
            const ulonglong2* Au = (const ulonglong2*)&d_ea_s[(size_t)e * 16];
            ulonglong2 a0 = Au[0], a1 = Au[1], a2 = Au[2], a3 = Au[3];
            ulonglong2 b0 = Au[4], b1 = Au[5], b2 = Au[6], b3 = Au[7];
            edge_accum(wq0, wq1, wq2, wq3, a0, a1, a2, a3, dp, spA, acc0, acc1);
            edge_accum(wq0, wq1, wq2, wq3, b0, b1, b2, b3, dp, spB, acc0, acc1);
        }
        if (e < e1) {
            int sA = d_esrc[e];
            float4 spA = *(const float4*)&d_P[(size_t)sA * 256 + 128 + lane * 4];
            const ulonglong2* Au = (const ulonglong2*)&d_ea_s[(size_t)e * 16];
            ulonglong2 a0 = Au[0], a1 = Au[1], a2 = Au[2], a3 = Au[3];
            edge_accum(wq0, wq1, wq2, wq3, a0, a1, a2, a3, dp, spA, acc0, acc1);
        }

        float2 xv;
        if (layer) {
            float2 tv = *(const float2*)&d_y0[(size_t)row * 64 + c0];
            xv = make_float2(tv.x * rs.x + rh.x, tv.y * rs.y + rh.y);
        } else {
            xv = *(const float2*)&x_in[(size_t)row * 64 + c0];
        }
        float o0 = xv.x + acc0, o1 = xv.y + acc1;
        *(float2*)&y[(size_t)row * 64 + c0] = make_float2(o0, o1);
        st_s0 += o0; st_q0 = fmaf(o0, o0, st_q0);
        st_s1 += o1; st_q1 = fmaf(o1, o1, st_q1);
    }

    // block-level BN partials
    sS[warp][c0] = st_s0; sS[warp][c0 + 1] = st_s1;
    sQ[warp][c0] = st_q0; sQ[warp][c0 + 1] = st_q1;
    __syncthreads();
    if (threadIdx.x < 64) {
        int c = threadIdx.x;
        d_psum[blockIdx.x * 64 + c] = sS[0][c] + sS[1][c] + sS[2][c] + sS[3][c];
        d_psq[blockIdx.x * 64 + c]  = sQ[0][c] + sQ[1][c] + sQ[2][c] + sQ[3][c];
    }
}

// ---------------- finalize BN stats from csr-block partials ----------------
__global__ __launch_bounds__(256) void finalize_stats_kernel(int layer, const float* __restrict__ gamma,
                                                             const float* __restrict__ beta) {
    __shared__ double shS[256], shQ[256];
    int t = threadIdx.x;
    int c = t & 63, sl = t >> 6;
    double s = 0.0, q = 0.0;
    for (int b = sl; b < NB_CSR; b += 4) {
        s += (double)d_psum[b * 64 + c];
        q += (double)d_psq[b * 64 + c];
    }
    shS[t] = s; shQ[t] = q;
    __syncthreads();
    if (t < 64) {
        double S = shS[t] + shS[t + 64] + shS[t + 128] + shS[t + 192];
        double Q = shQ[t] + shQ[t + 64] + shQ[t + 128] + shQ[t + 192];
        double m = S / (double)N_NODES;
        double v = Q / (double)N_NODES - m * m;
        double sc = (double)gamma[c] * rsqrt(v + 1e-5);
        d_scale[layer][c] = (float)sc;
        d_shift[layer][c] = (float)((double)beta[c] - m * sc);
    }
}

// ---------------- graph boundaries via binary search ----------------
__global__ void bounds_kernel(const void* __restrict__ batch_raw) {
    int g = threadIdx.x;
    if (g > 64) return;
    const int b64 = d_b64;
    const long long* bL = (const long long*)batch_raw;
    const int*       bI = (const int*)batch_raw;
    int lo = 0, hi = N_NODES;
    while (lo < hi) {
        int mid = (lo + hi) >> 1;
        long long bv = b64 ? bL[mid] : (long long)bI[mid];
        if (bv < (long long)g) lo = mid + 1; else hi = mid;
    }
    d_bound[g] = lo;
}

// BN(layer1) fused with global-mean-pool: one block per graph
__global__ __launch_bounds__(256) void pool_kernel(float* __restrict__ out) {
    __shared__ float sred[256];
    int g = blockIdx.x;
    int t = threadIdx.x;
    int c = t & 63, sub = t >> 6;
    int r0 = d_bound[g], r1 = d_bound[g + 1];
    float sc = d_scale[1][c], sh = d_shift[1][c];
    float acc = 0.f;
    for (int r = r0 + sub; r < r1; r += 4)
        acc += d_y1[(size_t)r * 64 + c] * sc + sh;
    sred[t] = acc;
    __syncthreads();
    if (t < 128) sred[t] += sred[t + 128];
    __syncthreads();
    if (t < 64) {
        float total = sred[t] + sred[t + 64];
        float cnt = (float)(r1 - r0);
        out[g * 64 + c] = total / fmaxf(cnt, 1.f);
    }
}

// ---------------- launch ----------------
extern "C" void kernel_launch(void* const* d_in, const int* in_sizes, int n_in,
                              void* d_out, int out_size) {
    const float* x     = (const float*)d_in[0];
    const void*  ei    = d_in[1];
    const float* ea    = (const float*)d_in[2];
    const void*  batch = d_in[3];
    const float *Wf0 = (const float*)d_in[4],  *bf0 = (const float*)d_in[5];
    const float *Ws0 = (const float*)d_in[6],  *bs0 = (const float*)d_in[7];
    const float *g0  = (const float*)d_in[8],  *be0 = (const float*)d_in[9];
    const float *Wf1 = (const float*)d_in[10], *bf1 = (const float*)d_in[11];
    const float *Ws1 = (const float*)d_in[12], *bs1 = (const float*)d_in[13];
    const float *g1  = (const float*)d_in[14], *be1 = (const float*)d_in[15];
    float* out = (float*)d_out;

    const int nodeBlocks = (N_NODES + 63) / 64;          // 782
    const int edgeGrid   = (E_EDGES + 255) / 256;        // 3125

    zero_detect_kernel<<<NB_SCAN, 256>>>((const int*)ei, (const int*)batch);
    prep_kernel<<<512, 256>>>(ei, Wf0, Ws0, bf0, bs0, Wf1, Ws1, bf1, bs1);
    scan1_kernel<<<NB_SCAN, 256>>>();
    scan2_kernel<<<1, 256>>>();
    scan3_kernel<<<NB_SCAN, 256>>>();
    scatter_kernel<<<edgeGrid, 256>>>(ea);
    bounds_kernel<<<1, 128>>>(batch);

    // layer 0 (stats fused into csr)
    node_gemm_kernel<<<nodeBlocks, 256>>>(x, 0);
    csr_kernel<<<NB_CSR, 128>>>(x, 0);
    finalize_stats_kernel<<<1, 256>>>(0, g0, be0);

    // layer 1 (BN0 folded into node_gemm input + csr residual)
    node_gemm_kernel<<<nodeBlocks, 256>>>(x, 1);
    csr_kernel<<<NB_CSR, 128>>>(x, 1);
    finalize_stats_kernel<<<1, 256>>>(1, g1, be1);

    // pool + output
    pool_kernel<<<64, 256>>>(out);
}